// round 17
// baseline (speedup 1.0000x reference)
#include <cuda_runtime.h>
#include <cuda_fp16.h>
#include <math.h>
#include <stdint.h>

#define EMBED   768
#define HEADS   8
#define HDIM    96
#define DEPTH   12
#define MLPH    3072
#define NP      1568
#define BATCH   2
#define NTOK    (BATCH*NP)      // 3136
#define KPATCH  1536

typedef __half h16;

// ---------------- scratch (device globals: allocation-free) ----------------
__device__ __align__(256) h16   g_imh [NTOK*KPATCH];
__device__ __align__(256) float g_h   [NTOK*EMBED];
__device__ __align__(256) h16   g_yh  [NTOK*EMBED];
__device__ __align__(256) h16   g_qkvh[NTOK*3*EMBED];
__device__ __align__(256) h16   g_aoh [NTOK*EMBED];
__device__ __align__(256) h16   g_mlph[NTOK*MLPH];
__device__ float g_pool[BATCH*EMBED];
__device__ float g_pln [BATCH*EMBED];
__device__ double g_freq[EMBED/2];
// weights: all hi-only fp16 (1-term)
__device__ __align__(256) h16 g_cwh[EMBED*KPATCH];
__device__ __align__(256) h16 g_qwh[DEPTH*3*EMBED*EMBED];
__device__ __align__(256) h16 g_owh[DEPTH*EMBED*EMBED];
__device__ __align__(256) h16 g_w1h[DEPTH*MLPH*EMBED];
__device__ __align__(256) h16 g_w2h[DEPTH*EMBED*MLPH];

#define LDSM4(R, addr) \
    asm volatile("ldmatrix.sync.aligned.m8n8.x4.shared.b16 {%0,%1,%2,%3},[%4];" \
        : "=r"((R)[0]), "=r"((R)[1]), "=r"((R)[2]), "=r"((R)[3]) : "r"(addr))

#define LDSM4T(R, addr) \
    asm volatile("ldmatrix.sync.aligned.m8n8.x4.trans.shared.b16 {%0,%1,%2,%3},[%4];" \
        : "=r"((R)[0]), "=r"((R)[1]), "=r"((R)[2]), "=r"((R)[3]) : "r"(addr))

#define MMA_F32(C, A, B0, B1) \
    asm volatile("mma.sync.aligned.m16n8k16.row.col.f32.f16.f16.f32 " \
        "{%0,%1,%2,%3},{%4,%5,%6,%7},{%8,%9},{%0,%1,%2,%3};" \
        : "+f"((C)[0]), "+f"((C)[1]), "+f"((C)[2]), "+f"((C)[3]) \
        : "r"((A)[0]), "r"((A)[1]), "r"((A)[2]), "r"((A)[3]), "r"(B0), "r"(B1))

__device__ __forceinline__ void cpa16(uint32_t dst, const void* src, bool p)
{
    int sz = p ? 16 : 0;
    asm volatile("cp.async.cg.shared.global [%0],[%1],16,%2;\n"
                 :: "r"(dst), "l"(src), "r"(sz));
}

// ================= GEMM: fp16 1-term, BM=64 x BN=128, 2 CTAs/SM ===========
// 8 warps = 2m x 4n, warp tile 32x32. Grid fits waves cleanly (49 M-tiles).
#define BK 32
#define SA 40
#define GBM 64
#define GBN 128
#define GSTAGE ((GBM + GBN) * SA)      // per-stage elems
#define GSMEM  (GSTAGE * 2 * 3)        // 46,080 B -> 2 CTAs/SM

template<int EPI, int OUT>
__global__ void __launch_bounds__(256, 2)
mma17_gemm(const h16* __restrict__ Agh, const h16* __restrict__ Bgh,
           const float* __restrict__ bias, const float* __restrict__ R,
           float* __restrict__ Cf, h16* __restrict__ Ch,
           int M, int N, int K, int lda, int ldb, int ldc, int ldr)
{
    constexpr int OFFB = GBM * SA;

    extern __shared__ __align__(16) h16 smem[];
    const uint32_t su = (uint32_t)__cvta_generic_to_shared(smem);

    const int tid  = threadIdx.x;
    const int lane = tid & 31;
    const int w    = tid >> 5;
    const int wm   = w >> 2;              // 0..1
    const int wn   = w & 3;               // 0..3
    const int m0   = blockIdx.y * GBM;
    const int n0   = blockIdx.x * GBN;

    float c[2][2][4];                     // [mi][nf(2 per NPR=2)][4] -> warp 32x32
    #pragma unroll
    for (int i = 0; i < 2; i++)
        #pragma unroll
        for (int j = 0; j < 2; j++)
            #pragma unroll
            for (int q = 0; q < 4; q++) c[i][j][q] = 0.f;
    float c2[2][2][4];
    #pragma unroll
    for (int i = 0; i < 2; i++)
        #pragma unroll
        for (int j = 0; j < 2; j++)
            #pragma unroll
            for (int q = 0; q < 4; q++) c2[i][j][q] = 0.f;

    const int lrow = lane & 15;
    const int lcol = (lane >> 4) * 8;
    const uint32_t aoffA = (uint32_t)(((wm*32 + lrow)*SA + lcol) * 2);
    const uint32_t boffB = (uint32_t)(((wn*32 + lrow)*SA + lcol) * 2);

    const int T = K / BK;

    auto issue = [&](int t, int s) {
        const int k0 = t * BK;
        const uint32_t sb = su + (uint32_t)(s * GSTAGE) * 2u;
        {   // A: 64 rows x 4 chunks = 256 chunks
            const int row = tid >> 2;
            const int kc  = (tid & 3) << 3;
            const bool p  = (m0 + row) < M;
            const h16* src = Agh + (long long)(p ? (m0 + row) : 0) * lda + k0 + kc;
            cpa16(sb + (uint32_t)(row*SA + kc) * 2u, src, p);
        }
        #pragma unroll
        for (int i = 0; i < 2; i++) {      // B: 128 rows x 4 chunks = 512
            const int ch  = (i << 8) + tid;
            const int row = ch >> 2;
            const int kc  = (ch & 3) << 3;
            const bool p  = (n0 + row) < N;
            const h16* src = Bgh + (long long)(p ? (n0 + row) : 0) * ldb + k0 + kc;
            cpa16(sb + (uint32_t)(OFFB + row*SA + kc) * 2u, src, p);
        }
    };

    issue(0, 0);
    asm volatile("cp.async.commit_group;");
    if (T > 1) { issue(1, 1); asm volatile("cp.async.commit_group;"); }

    for (int t = 0; t < T; t++) {
        if (t + 1 < T) asm volatile("cp.async.wait_group 1;");
        else           asm volatile("cp.async.wait_group 0;");
        __syncthreads();

        if (t + 2 < T) {
            issue(t + 2, (t + 2) % 3);
            asm volatile("cp.async.commit_group;");
        }

        const int s = t % 3;
        const uint32_t sb  = su + (uint32_t)(s * GSTAGE) * 2u;
        const uint32_t aHb = sb + aoffA;
        const uint32_t bHb = sb + (uint32_t)OFFB * 2u + boffB;

        #pragma unroll
        for (int kk2 = 0; kk2 < 2; kk2++) {
            const uint32_t kb = (uint32_t)(kk2 * 32);
            uint32_t Ahf[2][4], Bhf[2][4];
            LDSM4(Ahf[0], aHb + kb);                               // mi=0 covers 16 rows
            LDSM4(Ahf[1], aHb + (uint32_t)(16*SA*2) + kb);
            LDSM4(Bhf[0], bHb + kb);
            LDSM4(Bhf[1], bHb + (uint32_t)(16*SA*2) + kb);
            #pragma unroll
            for (int mi = 0; mi < 2; mi++) {
                MMA_F32(c [mi][0], Ahf[mi], Bhf[0][0], Bhf[0][2]);
                MMA_F32(c [mi][1], Ahf[mi], Bhf[0][1], Bhf[0][3]);
                MMA_F32(c2[mi][0], Ahf[mi], Bhf[1][0], Bhf[1][2]);
                MMA_F32(c2[mi][1], Ahf[mi], Bhf[1][1], Bhf[1][3]);
            }
        }
    }

    const int g  = lane >> 2;
    const int tq = lane & 3;
    #pragma unroll
    for (int pr = 0; pr < 2; pr++) {
        #pragma unroll
        for (int mi = 0; mi < 2; mi++) {
            #pragma unroll
            for (int nf = 0; nf < 2; nf++) {
                float* cc = pr ? c2[mi][nf] : c[mi][nf];
                int col = n0 + wn*32 + pr*16 + nf*8 + tq*2;
                #pragma unroll
                for (int half = 0; half < 2; half++) {
                    int row = m0 + wm*32 + mi*16 + g + half*8;
                    if (row >= M || col >= N) continue;
                    float v0 = cc[half*2 + 0];
                    float v1 = cc[half*2 + 1];
                    if (EPI == 1 || EPI == 2 || EPI == 4) { v0 += bias[col]; v1 += bias[col+1]; }
                    if (EPI == 2) {
                        v0 = 0.5f * v0 * (1.0f + erff(v0 * 0.70710678118654752f));
                        v1 = 0.5f * v1 * (1.0f + erff(v1 * 0.70710678118654752f));
                    }
                    if (EPI >= 3) {
                        float2 r2 = *(const float2*)&R[(long long)row*ldr + col];
                        v0 += r2.x; v1 += r2.y;
                    }
                    if (OUT == 0) {
                        float2 o; o.x = v0; o.y = v1;
                        *(float2*)&Cf[(long long)row*ldc + col] = o;
                    } else {
                        *(__half2*)&Ch[(long long)row*ldc + col] =
                            __halves2half2(__float2half_rn(v0), __float2half_rn(v1));
                    }
                }
            }
        }
    }
}

// ================= flash attention: KT=64, V via ldmatrix.trans ============
#define QSTR 104
#define PSTR 72
#define KTILES 25
#define F_OQ  0
#define F_OK  (128*QSTR)
#define F_OV  (F_OK + 2*64*QSTR)
#define F_OP  (F_OV + 2*64*QSTR)
#define F_ELEMS (F_OP + 128*PSTR)
#define F_SMEM (F_ELEMS*2 + 2*256*4)

__global__ void __launch_bounds__(256, 2)
flash_kernel(const h16* __restrict__ qkv, h16* __restrict__ ao)
{
    extern __shared__ __align__(16) h16 smem[];
    const uint32_t su = (uint32_t)__cvta_generic_to_shared(smem);
    float* statm = (float*)(smem + F_ELEMS);
    float* stats = statm + 256;

    const int tid = threadIdx.x, lane = tid & 31, w = tid >> 5;
    const int wm = w >> 1, wn = w & 1;
    const int g = lane >> 2, tq = lane & 3;
    const int z = blockIdx.z, bb = z >> 3, hh = z & 7;
    const int m0 = blockIdx.y * 128;

    const h16* Qg = qkv + (long long)bb*NP*(3*EMBED) + hh*HDIM;
    const h16* Kg = Qg + EMBED;
    const h16* Vg = Qg + 2*EMBED;
    h16* AOg = ao + (long long)bb*NP*EMBED + hh*HDIM;

    #pragma unroll
    for (int i = 0; i < 6; i++) {
        int ch = i*256 + tid;
        int row = ch / 12, c16 = ch % 12;
        bool p = (m0 + row) < NP;
        cpa16(su + (uint32_t)((F_OQ + row*QSTR + c16*8) * 2),
              Qg + (long long)(p ? (m0 + row) : 0)*(3*EMBED) + c16*8, p);
    }

    auto issueKV = [&](int t, int s) {
        const int k0 = t * 64;
        #pragma unroll
        for (int i = 0; i < 3; i++) {
            int ch = i*256 + tid;
            int row = ch / 12, c16 = ch % 12;
            bool p = (k0 + row) < NP;
            cpa16(su + (uint32_t)((F_OK + s*64*QSTR + row*QSTR + c16*8) * 2),
                  Kg + (long long)(p ? (k0 + row) : 0)*(3*EMBED) + c16*8, p);
        }
        #pragma unroll
        for (int i = 0; i < 3; i++) {
            int ch = i*256 + tid;
            int row = ch / 12, c16 = ch % 12;
            bool p = (k0 + row) < NP;
            cpa16(su + (uint32_t)((F_OV + s*64*QSTR + row*QSTR + c16*8) * 2),
                  Vg + (long long)(p ? (k0 + row) : 0)*(3*EMBED) + c16*8, p);
        }
    };

    issueKV(0, 0);
    asm volatile("cp.async.commit_group;");

    const int lrow = lane & 15;
    const int lcol = (lane >> 4) * 8;
    const uint32_t qoff  = su + (uint32_t)((F_OQ + (wm*32 + lrow)*QSTR + lcol) * 2);
    const uint32_t poffA = su + (uint32_t)((F_OP + (wm*32 + lrow)*PSTR + lcol) * 2);
    const int vkrow = (lane & 7) + ((lane >> 4) & 1) * 8;
    const int vncol = ((lane >> 3) & 1) * 8;
    const uint32_t voffB = su + (uint32_t)((F_OV + vkrow*QSTR + wn*48 + vncol) * 2);
    const int rbase = wm*32 + g;

    float o[2][6][4];
    float m_run[2][2], l_run[2][2], scl[2][2];
    #pragma unroll
    for (int mi = 0; mi < 2; mi++) {
        #pragma unroll
        for (int nf = 0; nf < 6; nf++)
            #pragma unroll
            for (int q = 0; q < 4; q++) o[mi][nf][q] = 0.f;
        m_run[mi][0] = m_run[mi][1] = -1e30f;
        l_run[mi][0] = l_run[mi][1] = 0.f;
    }

    for (int t = 0; t < KTILES; t++) {
        asm volatile("cp.async.wait_group 0;");
        __syncthreads();
        if (t + 1 < KTILES) {
            issueKV(t + 1, (t + 1) & 1);
            asm volatile("cp.async.commit_group;");
        }

        const int s = t & 1;
        const uint32_t koff = su + (uint32_t)((F_OK + s*64*QSTR + (wn*32 + lrow)*QSTR + lcol) * 2);
        const uint32_t voff = voffB + (uint32_t)(s*64*QSTR * 2);

        float c[2][4][4];
        #pragma unroll
        for (int mi = 0; mi < 2; mi++)
            #pragma unroll
            for (int nf = 0; nf < 4; nf++)
                #pragma unroll
                for (int q = 0; q < 4; q++) c[mi][nf][q] = 0.f;
        #pragma unroll
        for (int kci = 0; kci < 6; kci++) {
            const uint32_t kb = (uint32_t)(kci * 32);
            uint32_t Af[2][4], Bf[2][4];
            LDSM4(Af[0], qoff + kb);
            LDSM4(Af[1], qoff + (uint32_t)(16*QSTR*2) + kb);
            LDSM4(Bf[0], koff + kb);
            LDSM4(Bf[1], koff + (uint32_t)(16*QSTR*2) + kb);
            #pragma unroll
            for (int mi = 0; mi < 2; mi++)
                #pragma unroll
                for (int pr = 0; pr < 2; pr++) {
                    MMA_F32(c[mi][2*pr  ], Af[mi], Bf[pr][0], Bf[pr][2]);
                    MMA_F32(c[mi][2*pr+1], Af[mi], Bf[pr][1], Bf[pr][3]);
                }
        }
        if (t == KTILES - 1) {
            #pragma unroll
            for (int nf = 0; nf < 4; nf++) {
                int col0 = t*64 + wn*32 + nf*8 + tq*2;
                if (col0 >= NP)     { c[0][nf][0]=c[0][nf][2]=c[1][nf][0]=c[1][nf][2]=-1e30f; }
                if (col0 + 1 >= NP) { c[0][nf][1]=c[0][nf][3]=c[1][nf][1]=c[1][nf][3]=-1e30f; }
            }
        }
        #pragma unroll
        for (int mi = 0; mi < 2; mi++)
            #pragma unroll
            for (int qh = 0; qh < 2; qh++) {
                float v = -1e30f;
                #pragma unroll
                for (int nf = 0; nf < 4; nf++)
                    v = fmaxf(v, fmaxf(c[mi][nf][qh*2], c[mi][nf][qh*2+1]));
                v = fmaxf(v, __shfl_xor_sync(0xffffffffu, v, 1));
                v = fmaxf(v, __shfl_xor_sync(0xffffffffu, v, 2));
                if (tq == 0) statm[(rbase + mi*16 + qh*8)*2 + wn] = v;
            }
        __syncthreads();
        #pragma unroll
        for (int mi = 0; mi < 2; mi++)
            #pragma unroll
            for (int qh = 0; qh < 2; qh++) {
                const int r = rbase + mi*16 + qh*8;
                float tm = fmaxf(statm[r*2], statm[r*2+1]);
                float mn = fmaxf(m_run[mi][qh], tm);
                float sc = __expf(m_run[mi][qh] - mn);
                m_run[mi][qh] = mn; scl[mi][qh] = sc;
                #pragma unroll
                for (int nf = 0; nf < 6; nf++) {
                    o[mi][nf][qh*2  ] *= sc;
                    o[mi][nf][qh*2+1] *= sc;
                }
                float ps = 0.f;
                #pragma unroll
                for (int nf = 0; nf < 4; nf++) {
                    float p0 = __expf(c[mi][nf][qh*2  ] - mn);
                    float p1 = __expf(c[mi][nf][qh*2+1] - mn);
                    ps += p0 + p1;
                    *(__half2*)(smem + F_OP + (wm*32 + mi*16 + g + qh*8)*PSTR
                                + wn*32 + nf*8 + tq*2) =
                        __halves2half2(__float2half_rn(p0), __float2half_rn(p1));
                }
                ps += __shfl_xor_sync(0xffffffffu, ps, 1);
                ps += __shfl_xor_sync(0xffffffffu, ps, 2);
                if (tq == 0) stats[r*2 + wn] = ps;
            }
        __syncthreads();
        #pragma unroll
        for (int mi = 0; mi < 2; mi++)
            #pragma unroll
            for (int qh = 0; qh < 2; qh++) {
                const int r = rbase + mi*16 + qh*8;
                l_run[mi][qh] = l_run[mi][qh]*scl[mi][qh] + stats[r*2] + stats[r*2+1];
            }
        #pragma unroll
        for (int kci = 0; kci < 4; kci++) {
            uint32_t Af[2][4], Bf[3][4];
            LDSM4(Af[0], poffA + (uint32_t)(kci*32));
            LDSM4(Af[1], poffA + (uint32_t)(16*PSTR*2) + (uint32_t)(kci*32));
            #pragma unroll
            for (int pr = 0; pr < 3; pr++)
                LDSM4T(Bf[pr], voff + (uint32_t)((kci*16*QSTR + pr*16) * 2));
            #pragma unroll
            for (int mi = 0; mi < 2; mi++)
                #pragma unroll
                for (int pr = 0; pr < 3; pr++) {
                    MMA_F32(o[mi][2*pr  ], Af[mi], Bf[pr][0], Bf[pr][2]);
                    MMA_F32(o[mi][2*pr+1], Af[mi], Bf[pr][1], Bf[pr][3]);
                }
        }
    }

    #pragma unroll
    for (int mi = 0; mi < 2; mi++)
        #pragma unroll
        for (int qh = 0; qh < 2; qh++) {
            const int row = m0 + rbase + mi*16 + qh*8;
            if (row >= NP) continue;
            const float inv = 1.0f / l_run[mi][qh];
            #pragma unroll
            for (int nf = 0; nf < 6; nf++) {
                const int col = wn*48 + nf*8 + tq*2;
                float v0 = o[mi][nf][qh*2  ] * inv;
                float v1 = o[mi][nf][qh*2+1] * inv;
                *(__half2*)&AOg[(long long)row*EMBED + col] =
                    __halves2half2(__float2half_rn(v0), __float2half_rn(v1));
            }
        }
}

// ---------------- fp32 -> fp16 convert (hi only) ----------
__global__ void tohalf_kernel(const float* __restrict__ s, h16* __restrict__ h,
                              long long n)
{
    long long i = ((long long)blockIdx.x*256 + threadIdx.x)*4;
    if (i >= n) return;
    float4 v = *(const float4*)&s[i];
    *(__half2*)&h[i  ] = __halves2half2(__float2half_rn(v.x), __float2half_rn(v.y));
    *(__half2*)&h[i+2] = __halves2half2(__float2half_rn(v.z), __float2half_rn(v.w));
}

// ---------------- layernorm (fp32 out OR fp16-hi out) ----------------
__global__ void ln_kernel(const float* __restrict__ X, const float* __restrict__ sc,
                          const float* __restrict__ bi, float* __restrict__ Yf,
                          h16* __restrict__ Yh, int Cn)
{
    const float* x = X + (long long)blockIdx.x * Cn;
    __shared__ float sh1[32], sh2[32];
    int tid = threadIdx.x;
    float s = 0.f, s2 = 0.f;
    for (int i = tid; i < Cn; i += 256) { float v = x[i]; s += v; s2 += v*v; }
    #pragma unroll
    for (int o = 16; o > 0; o >>= 1) {
        s  += __shfl_xor_sync(0xffffffffu, s,  o);
        s2 += __shfl_xor_sync(0xffffffffu, s2, o);
    }
    if ((tid & 31) == 0) { sh1[tid>>5] = s; sh2[tid>>5] = s2; }
    __syncthreads();
    if (tid < 32) {
        float a = (tid < 8) ? sh1[tid] : 0.f;
        float b = (tid < 8) ? sh2[tid] : 0.f;
        #pragma unroll
        for (int o = 4; o > 0; o >>= 1) {
            a += __shfl_xor_sync(0xffffffffu, a, o);
            b += __shfl_xor_sync(0xffffffffu, b, o);
        }
        if (tid == 0) { sh1[0] = a; sh2[0] = b; }
    }
    __syncthreads();
    float mean = sh1[0] / Cn;
    float var  = sh2[0] / Cn - mean*mean;
    float inv  = rsqrtf(var + 1e-5f);
    for (int i = tid; i < Cn; i += 256) {
        float v = (x[i] - mean) * inv * sc[i] + bi[i];
        if (Yf) Yf[(long long)blockIdx.x*Cn + i] = v;
        else    Yh[(long long)blockIdx.x*Cn + i] = __float2half_rn(v);
    }
}

// ---------------- im2col (writes fp16 hi only) ----------------
__global__ void im2col_kernel(const float* __restrict__ x)
{
    long long idx = (long long)blockIdx.x * 256 + threadIdx.x;
    if (idx >= (long long)NTOK * KPATCH) return;
    int j = (int)(idx % KPATCH);
    int m = (int)(idx / KPATCH);
    int b = m / NP, n = m % NP;
    int t = n / 196, r = n % 196, yy = r / 14, xx = r % 14;
    int i  = j / 512, r2 = j % 512;
    int dt = r2 / 256, r3 = r2 % 256;
    int dy = r3 / 16,  dx = r3 % 16;
    long long off = ((((long long)(b*3 + i)*16 + (2*t + dt))*224) + (16*yy + dy))*224 + (16*xx + dx);
    g_imh[idx] = __float2half_rn(x[off]);
}

// ---------------- positional encoding ----------------
__global__ void freq_kernel()
{
    int c2 = threadIdx.x;
    if (c2 < EMBED/2) g_freq[c2] = pow(10000.0, -2.0 * c2 / (double)EMBED);
}
__global__ void posadd_kernel()
{
    int idx = blockIdx.x * 256 + threadIdx.x;
    if (idx >= NP*EMBED) return;
    int n = idx / EMBED, c = idx % EMBED;
    double a = (double)n * g_freq[c >> 1];
    const double TWO_PI = 6.283185307179586476925286766559;
    int k = (int)(a * (1.0 / TWO_PI) + 0.5);
    float rf = (float)(a - (double)k * TWO_PI);
    float v = (c & 1) ? cosf(rf) : sinf(rf);
    g_h[idx]            += v;
    g_h[idx + NP*EMBED] += v;
}

// ---------------- mean pool: coalesced block reduce ----------------
__global__ void pool_kernel()
{
    __shared__ float acc[2][128];
    const int b  = blockIdx.y;
    const int c0 = blockIdx.x * 128;
    const int tg = threadIdx.x >> 7;
    const int c  = threadIdx.x & 127;
    const float* base = g_h + (long long)b*NP*EMBED + c0 + c;
    float s = 0.f;
    for (int n = tg; n < NP; n += 2)
        s += base[(long long)n*EMBED];
    acc[tg][c] = s;
    __syncthreads();
    if (tg == 0)
        g_pool[b*EMBED + c0 + c] = (acc[0][c] + acc[1][c]) * (1.0f / NP);
}

// ---------------- classifier head ----------------
__global__ void head_kernel(const float* __restrict__ W, const float* __restrict__ hb,
                            float* __restrict__ out)
{
    int g = blockIdx.x * 256 + threadIdx.x;
    int warp = g >> 5, lane = g & 31;
    if (warp >= BATCH*1000) return;
    int b = warp / 1000, j = warp % 1000;
    float s = 0.f;
    for (int c = lane; c < EMBED; c += 32)
        s += g_pln[b*EMBED + c] * W[j*EMBED + c];
    #pragma unroll
    for (int o = 16; o > 0; o >>= 1) s += __shfl_xor_sync(0xffffffffu, s, o);
    if (lane == 0) out[warp] = s + hb[j];
}

// ---------------- host orchestration ----------------
extern "C" void kernel_launch(void* const* d_in, const int* in_sizes, int n_in,
                              void* d_out, int out_size)
{
    const float* x      = (const float*)d_in[0];
    const float* conv_w = (const float*)d_in[1];
    const float* conv_b = (const float*)d_in[2];
    const float* n1s    = (const float*)d_in[3];
    const float* n1b    = (const float*)d_in[4];
    const float* qkv_w  = (const float*)d_in[5];
    const float* out_w  = (const float*)d_in[6];
    const float* out_b  = (const float*)d_in[7];
    const float* n2s    = (const float*)d_in[8];
    const float* n2b    = (const float*)d_in[9];
    const float* fc1_w  = (const float*)d_in[10];
    const float* fc1_b  = (const float*)d_in[11];
    const float* fc2_w  = (const float*)d_in[12];
    const float* fc2_b  = (const float*)d_in[13];
    const float* fns    = (const float*)d_in[14];
    const float* fnb    = (const float*)d_in[15];
    const float* head_w = (const float*)d_in[16];
    const float* head_b = (const float*)d_in[17];
    float* out = (float*)d_out;

    float *h, *pool, *pln;
    h16 *imh,*yh,*qkvh,*aoh,*mlph;
    h16 *cwh,*qwh,*owh,*w1h,*w2h;
    cudaGetSymbolAddress((void**)&h,    g_h);
    cudaGetSymbolAddress((void**)&pool, g_pool);
    cudaGetSymbolAddress((void**)&pln,  g_pln);
    cudaGetSymbolAddress((void**)&imh,  g_imh);
    cudaGetSymbolAddress((void**)&yh,   g_yh);
    cudaGetSymbolAddress((void**)&qkvh, g_qkvh);
    cudaGetSymbolAddress((void**)&aoh,  g_aoh);
    cudaGetSymbolAddress((void**)&mlph, g_mlph);
    cudaGetSymbolAddress((void**)&cwh,  g_cwh);
    cudaGetSymbolAddress((void**)&qwh,  g_qwh);
    cudaGetSymbolAddress((void**)&owh,  g_owh);
    cudaGetSymbolAddress((void**)&w1h,  g_w1h);
    cudaGetSymbolAddress((void**)&w2h,  g_w2h);

    cudaFuncSetAttribute(mma17_gemm<1,0>, cudaFuncAttributeMaxDynamicSharedMemorySize, GSMEM);
    cudaFuncSetAttribute(mma17_gemm<0,1>, cudaFuncAttributeMaxDynamicSharedMemorySize, GSMEM);
    cudaFuncSetAttribute(mma17_gemm<4,0>, cudaFuncAttributeMaxDynamicSharedMemorySize, GSMEM);
    cudaFuncSetAttribute(mma17_gemm<2,1>, cudaFuncAttributeMaxDynamicSharedMemorySize, GSMEM);
    cudaFuncSetAttribute(flash_kernel, cudaFuncAttributeMaxDynamicSharedMemorySize, F_SMEM);

    // ---- weight prep (all fp16 hi) ----
    {
        long long n;
        n = (long long)EMBED*KPATCH;
        tohalf_kernel<<<(int)((n/4+255)/256),256>>>(conv_w, cwh, n);
        n = (long long)DEPTH*3*EMBED*EMBED;
        tohalf_kernel<<<(int)((n/4+255)/256),256>>>(qkv_w, qwh, n);
        n = (long long)DEPTH*EMBED*EMBED;
        tohalf_kernel<<<(int)((n/4+255)/256),256>>>(out_w, owh, n);
        n = (long long)DEPTH*MLPH*EMBED;
        tohalf_kernel<<<(int)((n/4+255)/256),256>>>(fc1_w, w1h, n);
        n = (long long)DEPTH*EMBED*MLPH;
        tohalf_kernel<<<(int)((n/4+255)/256),256>>>(fc2_w, w2h, n);
    }

    // ---- patch embed ----
    im2col_kernel<<<(int)(((long long)NTOK*KPATCH + 255)/256), 256>>>(x);
    {
        dim3 g(EMBED/GBN, (NTOK+GBM-1)/GBM, 1);
        mma17_gemm<1,0><<<g,256,GSMEM>>>(
            imh, cwh, conv_b, nullptr, h, nullptr,
            NTOK, EMBED, KPATCH, KPATCH, KPATCH, EMBED, 0);
    }
    freq_kernel<<<1, EMBED/2>>>();
    posadd_kernel<<<(NP*EMBED + 255)/256, 256>>>();

    // ---- transformer blocks ----
    for (int l = 0; l < DEPTH; l++) {
        h16* lqwh = qwh + (long long)l*3*EMBED*EMBED;
        h16* lowh = owh + (long long)l*EMBED*EMBED;
        h16* lw1h = w1h + (long long)l*MLPH*EMBED;
        h16* lw2h = w2h + (long long)l*EMBED*MLPH;
        const float* ob = out_b + (long long)l*EMBED;
        const float* b1 = fc1_b + (long long)l*MLPH;
        const float* b2 = fc2_b + (long long)l*EMBED;

        ln_kernel<<<NTOK,256>>>(h, n1s + l*EMBED, n1b + l*EMBED, nullptr, yh, EMBED);

        {   // qkv = y @ qw^T  (882 blocks = 2.98 waves @2/SM)
            dim3 g((3*EMBED)/GBN, (NTOK+GBM-1)/GBM, 1);
            mma17_gemm<0,1><<<g,256,GSMEM>>>(
                yh, lqwh, nullptr, nullptr, nullptr, qkvh,
                NTOK, 3*EMBED, EMBED, EMBED, EMBED, 3*EMBED, 0);
        }

        {   // fused attention
            dim3 g(1, 13, BATCH*HEADS);
            flash_kernel<<<g,256,F_SMEM>>>(qkvh, aoh);
        }

        {   // h = h + ao @ ow^T + ob  (294 blocks = 0.99 waves)
            dim3 g(EMBED/GBN, (NTOK+GBM-1)/GBM, 1);
            mma17_gemm<4,0><<<g,256,GSMEM>>>(
                aoh, lowh, ob, h, h, nullptr,
                NTOK, EMBED, EMBED, EMBED, EMBED, EMBED, EMBED);
        }

        ln_kernel<<<NTOK,256>>>(h, n2s + l*EMBED, n2b + l*EMBED, nullptr, yh, EMBED);

        {   // mlp = gelu(y @ w1^T + b1)  (1176 blocks = 3.97 waves)
            dim3 g(MLPH/GBN, (NTOK+GBM-1)/GBM, 1);
            mma17_gemm<2,1><<<g,256,GSMEM>>>(
                yh, lw1h, b1, nullptr, nullptr, mlph,
                NTOK, MLPH, EMBED, EMBED, EMBED, MLPH, 0);
        }

        {   // h = h + mlp @ w2^T + b2  (294 blocks = 0.99 waves)
            dim3 g(EMBED/GBN, (NTOK+GBM-1)/GBM, 1);
            mma17_gemm<4,0><<<g,256,GSMEM>>>(
                mlph, lw2h, b2, h, h, nullptr,
                NTOK, EMBED, MLPH, MLPH, MLPH, EMBED, EMBED);
        }
    }

    // ---- pooled head ----
    {
        dim3 g(EMBED/128, BATCH);
        pool_kernel<<<g,256>>>();
    }
    ln_kernel<<<BATCH,256>>>(pool, fns, fnb, pln, nullptr, EMBED);
    head_kernel<<<(BATCH*1000*32 + 255)/256, 256>>>(head_w, head_b, out);
}